// round 4
// baseline (speedup 1.0000x reference)
#include <cuda_runtime.h>

// Problem constants
#define B   128
#define S   37
#define T   2048
#define D   256
#define STC 8
#define C   2
#define MERGED 264     // D + STC
#define F2  74         // 2*S features
#define NT  256        // threads per block
#define NW  8          // warps per block
#define G   (T/4)      // 512 float4 groups along time
#define PB  8          // time partitions per batch
#define GP  (G/PB)     // 64 float4 groups per partition

// Partial sums: [b][p][74 feature sums, masked time sum, denom]
// Every reduce CTA (b,p) writes its whole 76-float slice -> no init, no atomics.
__device__ float g_part[B][PB][F2 + 2];

__device__ __forceinline__ float warp_sum(float v) {
#pragma unroll
    for (int o = 16; o; o >>= 1) v += __shfl_xor_sync(0xffffffffu, v, o);
    return v;
}

// ---------------------------------------------------------------------------
// Kernel 1: streaming reduction over time.  grid = B*PB, block = 256.
// Warp w owns sensors {w, w+8, ...} (<=5), lanes stride the 64 time-groups.
// ---------------------------------------------------------------------------
__global__ __launch_bounds__(NT, 3)
void reduce_kernel(const float* __restrict__ x,
                   const float* __restrict__ time_in,
                   const int*   __restrict__ smask)
{
    __shared__ unsigned vmask[GP];   // per-group 4-bit validity (1 bit per t)
    __shared__ float feat_s[F2];
    __shared__ float ssum_s[4];      // [0..1] tsum per warp, [2..3] denom per warp

    const int bp   = blockIdx.x;
    const int b    = bp >> 3;
    const int p    = bp & (PB - 1);
    const int tid  = threadIdx.x;
    const int lane = tid & 31;
    const int wid  = tid >> 5;

    if (tid < GP) vmask[tid] = 0u;
    __syncthreads();

    const float4* __restrict__ x4 = (const float4*)x     + (size_t)b * S * G;
    const int4*   __restrict__ m4 = (const int4*)smask   + (size_t)b * S * G;
    const int gbase = p * GP;

    float accx[5] = {0.f, 0.f, 0.f, 0.f, 0.f};
    float accm[5] = {0.f, 0.f, 0.f, 0.f, 0.f};
    const int ns = (wid < 5) ? 5 : 4;     // sensors this warp owns (37 = 5*5 + 3*4)

#pragma unroll
    for (int gi = 0; gi < GP / 32; gi++) {
        const int g = gbase + lane + gi * 32;
        unsigned bits = 0u;
#pragma unroll
        for (int i = 0; i < 5; i++) {
            if (i < ns) {                  // warp-uniform
                const int s = wid + 8 * i;
                const int idx = s * G + g;
                float4 xv = x4[idx];
                int4   mv = m4[idx];
                // Feature sums need no mask: invalid timestep => all features 0.
                accx[i] += (xv.x + xv.y) + (xv.z + xv.w);
                accm[i] += (float)((mv.x + mv.y) + (mv.z + mv.w));
                bits |= (xv.x != 0.f || mv.x != 0) ? 1u : 0u;
                bits |= (xv.y != 0.f || mv.y != 0) ? 2u : 0u;
                bits |= (xv.z != 0.f || mv.z != 0) ? 4u : 0u;
                bits |= (xv.w != 0.f || mv.w != 0) ? 8u : 0u;
            }
        }
        if (bits) atomicOr(&vmask[g - gbase], bits);
    }

    // per-sensor warp reduction; each sensor owned by exactly one warp
#pragma unroll
    for (int i = 0; i < 5; i++) {
        if (i < ns) {
            float vx = warp_sum(accx[i]);
            float vm = warp_sum(accm[i]);
            if (lane == 0) {
                const int s = wid + 8 * i;
                feat_s[s]     = vx;
                feat_s[S + s] = vm;
            }
        }
    }
    __syncthreads();

    // denom & masked time-sum from the assembled validity bitmask
    float dcnt = 0.f, tsum = 0.f;
    if (tid < GP) {
        const unsigned bits = vmask[tid];
        float4 tv = ((const float4*)time_in)[b * G + gbase + tid];
        dcnt = (float)__popc(bits & 0xFu);
        tsum = (bits & 1u ? tv.x : 0.f) + (bits & 2u ? tv.y : 0.f)
             + (bits & 4u ? tv.z : 0.f) + (bits & 8u ? tv.w : 0.f);
    }
    if (wid < 2) {
        float t = warp_sum(tsum);
        float d = warp_sum(dcnt);
        if (lane == 0) { ssum_s[wid] = t; ssum_s[2 + wid] = d; }
    }
    __syncthreads();

    float* __restrict__ dst = &g_part[b][p][0];
    if (tid < F2)          dst[tid]    = feat_s[tid];
    else if (tid == F2)    dst[F2]     = ssum_s[0] + ssum_s[1];
    else if (tid == F2 + 1) dst[F2 + 1] = ssum_s[2] + ssum_s[3];
}

// ---------------------------------------------------------------------------
// Kernel 2: head (pooled embedding -> merge -> classifier).  grid = B.
// ---------------------------------------------------------------------------
__global__ __launch_bounds__(NT, 1)
void head_kernel(const float* __restrict__ static_in,
                 const float* __restrict__ W_sensor,  // [74,256]
                 const float* __restrict__ b_sensor,  // [256]
                 const float* __restrict__ W_time,    // [1,256]
                 const float* __restrict__ b_time,    // [256]
                 const float* __restrict__ W_static,  // [8,8]
                 const float* __restrict__ b_static,  // [8]
                 const float* __restrict__ W_merge,   // [264,264]
                 const float* __restrict__ b_merge,   // [264]
                 const float* __restrict__ W_cls,     // [264,2]
                 const float* __restrict__ b_cls,     // [2]
                 float* __restrict__ out)             // [B,2]
{
    __shared__ float sfeat[F2];
    __shared__ float ssum[2];      // [0]=masked time sum, [1]=denom
    __shared__ float s_inv, s_r, s_ts;
    __shared__ float scomb[MERGED];
    __shared__ float ored[NW][2];

    const int b    = blockIdx.x;
    const int tid  = threadIdx.x;
    const int lane = tid & 31;
    const int wid  = tid >> 5;

    if (tid < F2 + 2) {
        float v = 0.f;
#pragma unroll
        for (int pp = 0; pp < PB; pp++) v += g_part[b][pp][tid];
        if (tid < F2) sfeat[tid] = v;
        else          ssum[tid - F2] = v;
    }
    __syncthreads();

    if (tid == 0) {
        float dn  = ssum[1];
        float inv = 1.f / fmaxf(dn, 1e-9f);
        s_inv = inv;
        s_r   = dn * inv;        // 1.0 normally, 0.0 if no valid step
        s_ts  = ssum[0] * inv;   // masked mean time
    }
    __syncthreads();

    const float inv = s_inv, r = s_r, ts = s_ts;

    // Phase B: pooled embedding (thread = output channel d) + static embedding
    {
        float acc = 0.f;
#pragma unroll
        for (int f = 0; f < F2; f++)
            acc = fmaf(sfeat[f], W_sensor[f * D + tid], acc);
        scomb[tid] = acc * inv
                   + r * (b_sensor[tid] + b_time[tid])
                   + ts * W_time[tid];
    }
    if (tid < STC) {
        float acc = b_static[tid];
#pragma unroll
        for (int k = 0; k < STC; k++)
            acc = fmaf(static_in[b * STC + k], W_static[k * STC + tid], acc);
        scomb[D + tid] = acc;
    }
    __syncthreads();

    // Phase C: merge (ReLU) + classifier
    float p0 = 0.f, p1 = 0.f;
    for (int j = tid; j < MERGED; j += NT) {
        float acc = b_merge[j];
#pragma unroll 8
        for (int k = 0; k < MERGED; k++)
            acc = fmaf(scomb[k], W_merge[k * MERGED + j], acc);
        acc = fmaxf(acc, 0.f);
        p0 = fmaf(acc, W_cls[j * C + 0], p0);
        p1 = fmaf(acc, W_cls[j * C + 1], p1);
    }
    p0 = warp_sum(p0);
    p1 = warp_sum(p1);
    if (lane == 0) { ored[wid][0] = p0; ored[wid][1] = p1; }
    __syncthreads();

    if (tid == 0) {
        float o0 = b_cls[0], o1 = b_cls[1];
#pragma unroll
        for (int w = 0; w < NW; w++) { o0 += ored[w][0]; o1 += ored[w][1]; }
        out[b * C + 0] = o0;
        out[b * C + 1] = o1;
    }
}

extern "C" void kernel_launch(void* const* d_in, const int* in_sizes, int n_in,
                              void* d_out, int out_size)
{
    const float* x        = (const float*)d_in[0];
    const float* stat     = (const float*)d_in[1];
    const float* time_in  = (const float*)d_in[2];
    const int*   smask    = (const int*)  d_in[3];
    const float* W_sensor = (const float*)d_in[4];
    const float* b_sensor = (const float*)d_in[5];
    const float* W_time   = (const float*)d_in[6];
    const float* b_time   = (const float*)d_in[7];
    const float* W_static = (const float*)d_in[8];
    const float* b_static = (const float*)d_in[9];
    const float* W_merge  = (const float*)d_in[10];
    const float* b_merge  = (const float*)d_in[11];
    const float* W_cls    = (const float*)d_in[12];
    const float* b_cls    = (const float*)d_in[13];
    float* out = (float*)d_out;

    reduce_kernel<<<B * PB, NT>>>(x, time_in, smask);
    head_kernel<<<B, NT>>>(stat,
                           W_sensor, b_sensor, W_time, b_time,
                           W_static, b_static, W_merge, b_merge,
                           W_cls, b_cls, out);
}

// round 6
// speedup vs baseline: 1.6667x; 1.6667x over previous
#include <cuda_runtime.h>

// Problem constants
#define B   128
#define S   37
#define T   2048
#define D   256
#define STC 8
#define C   2
#define MERGED 264     // D + STC
#define F2  74         // 2*S features
#define NT  256        // threads per block
#define G   (T/4)      // 512 float4 groups along time
#define PB  8          // time partitions per batch
#define GP  (G/PB)     // 64 float4 groups per partition

// Head tiling
#define BT      8      // batches per merge CTA
#define BTILES  (B/BT)         // 16
#define JT      32             // j columns per merge CTA
#define JTILES  ((MERGED+JT-1)/JT)  // 9 (last tile ragged)

// Scratch (device globals; every slot written by exactly one CTA -> deterministic)
__device__ float g_part[B][PB][F2 + 2];    // reduce partials
__device__ float g_comb[B][MERGED];        // pooled||static embedding
__device__ float g_partC[B][JTILES][2];    // classifier partials per j-tile

__device__ __forceinline__ float warp_sum(float v) {
#pragma unroll
    for (int o = 16; o; o >>= 1) v += __shfl_xor_sync(0xffffffffu, v, o);
    return v;
}

// ---------------------------------------------------------------------------
// Kernel 1: streaming reduction over time.  grid = B*PB, block = 256.
// Warp w owns sensors {w, w+8, ...} (<=5), lanes stride the 64 time-groups.
// ---------------------------------------------------------------------------
__global__ __launch_bounds__(NT, 3)
void reduce_kernel(const float* __restrict__ x,
                   const float* __restrict__ time_in,
                   const int*   __restrict__ smask)
{
    __shared__ unsigned vmask[GP];   // per-group 4-bit validity (1 bit per t)
    __shared__ float feat_s[F2];
    __shared__ float ssum_s[4];      // [0..1] tsum per warp, [2..3] denom per warp

    const int bp   = blockIdx.x;
    const int b    = bp >> 3;
    const int p    = bp & (PB - 1);
    const int tid  = threadIdx.x;
    const int lane = tid & 31;
    const int wid  = tid >> 5;

    if (tid < GP) vmask[tid] = 0u;
    __syncthreads();

    const float4* __restrict__ x4 = (const float4*)x     + (size_t)b * S * G;
    const int4*   __restrict__ m4 = (const int4*)smask   + (size_t)b * S * G;
    const int gbase = p * GP;

    float accx[5] = {0.f, 0.f, 0.f, 0.f, 0.f};
    float accm[5] = {0.f, 0.f, 0.f, 0.f, 0.f};
    const int ns = (wid < 5) ? 5 : 4;     // sensors this warp owns (37 = 5*5 + 3*4)

#pragma unroll
    for (int gi = 0; gi < GP / 32; gi++) {
        const int g = gbase + lane + gi * 32;
        unsigned bits = 0u;
#pragma unroll
        for (int i = 0; i < 5; i++) {
            if (i < ns) {                  // warp-uniform
                const int s = wid + 8 * i;
                const int idx = s * G + g;
                float4 xv = x4[idx];
                int4   mv = m4[idx];
                // Feature sums need no mask: invalid timestep => all features 0.
                accx[i] += (xv.x + xv.y) + (xv.z + xv.w);
                accm[i] += (float)((mv.x + mv.y) + (mv.z + mv.w));
                bits |= (xv.x != 0.f || mv.x != 0) ? 1u : 0u;
                bits |= (xv.y != 0.f || mv.y != 0) ? 2u : 0u;
                bits |= (xv.z != 0.f || mv.z != 0) ? 4u : 0u;
                bits |= (xv.w != 0.f || mv.w != 0) ? 8u : 0u;
            }
        }
        if (bits) atomicOr(&vmask[g - gbase], bits);
    }

    // per-sensor warp reduction; each sensor owned by exactly one warp
#pragma unroll
    for (int i = 0; i < 5; i++) {
        if (i < ns) {
            float vx = warp_sum(accx[i]);
            float vm = warp_sum(accm[i]);
            if (lane == 0) {
                const int s = wid + 8 * i;
                feat_s[s]     = vx;
                feat_s[S + s] = vm;
            }
        }
    }
    __syncthreads();

    // denom & masked time-sum from the assembled validity bitmask
    float dcnt = 0.f, tsum = 0.f;
    if (tid < GP) {
        const unsigned bits = vmask[tid];
        float4 tv = ((const float4*)time_in)[b * G + gbase + tid];
        dcnt = (float)__popc(bits & 0xFu);
        tsum = (bits & 1u ? tv.x : 0.f) + (bits & 2u ? tv.y : 0.f)
             + (bits & 4u ? tv.z : 0.f) + (bits & 8u ? tv.w : 0.f);
    }
    if (wid < 2) {
        float t = warp_sum(tsum);
        float d = warp_sum(dcnt);
        if (lane == 0) { ssum_s[wid] = t; ssum_s[2 + wid] = d; }
    }
    __syncthreads();

    float* __restrict__ dst = &g_part[b][p][0];
    if (tid < F2)           dst[tid]    = feat_s[tid];
    else if (tid == F2)     dst[F2]     = ssum_s[0] + ssum_s[1];
    else if (tid == F2 + 1) dst[F2 + 1] = ssum_s[2] + ssum_s[3];
}

// ---------------------------------------------------------------------------
// Kernel 2: embedding.  grid = B.  Writes g_comb[b][0..263].
// ---------------------------------------------------------------------------
__global__ __launch_bounds__(NT, 1)
void embed_kernel(const float* __restrict__ static_in,
                  const float* __restrict__ W_sensor,  // [74,256]
                  const float* __restrict__ b_sensor,  // [256]
                  const float* __restrict__ W_time,    // [1,256]
                  const float* __restrict__ b_time,    // [256]
                  const float* __restrict__ W_static,  // [8,8]
                  const float* __restrict__ b_static)  // [8]
{
    __shared__ float sfeat[F2];
    __shared__ float ssum[2];      // [0]=masked time sum, [1]=denom
    __shared__ float s_inv, s_r, s_ts;

    const int b   = blockIdx.x;
    const int tid = threadIdx.x;

    if (tid < F2 + 2) {
        float v = 0.f;
#pragma unroll
        for (int pp = 0; pp < PB; pp++) v += g_part[b][pp][tid];
        if (tid < F2) sfeat[tid] = v;
        else          ssum[tid - F2] = v;
    }
    __syncthreads();

    if (tid == 0) {
        float dn  = ssum[1];
        float inv = 1.f / fmaxf(dn, 1e-9f);
        s_inv = inv;
        s_r   = dn * inv;        // 1.0 normally, 0.0 if no valid step
        s_ts  = ssum[0] * inv;   // masked mean time
    }
    __syncthreads();

    const float inv = s_inv, r = s_r, ts = s_ts;

    {   // thread = output channel d; coalesced W_sensor rows
        float acc = 0.f;
#pragma unroll
        for (int f = 0; f < F2; f++)
            acc = fmaf(sfeat[f], W_sensor[f * D + tid], acc);
        g_comb[b][tid] = acc * inv
                       + r * (b_sensor[tid] + b_time[tid])
                       + ts * W_time[tid];
    }
    if (tid < STC) {
        float acc = b_static[tid];
#pragma unroll
        for (int k = 0; k < STC; k++)
            acc = fmaf(static_in[b * STC + k], W_static[k * STC + tid], acc);
        g_comb[b][D + tid] = acc;
    }
}

// ---------------------------------------------------------------------------
// Kernel 3: merge GEMM + classifier partials.
// grid = (JTILES, BTILES) = (9,16) = 144 CTAs, block = 256.
// Warp w owns batch b0+w; lane owns column j0+lane. W tile + comb tile in smem.
// ---------------------------------------------------------------------------
__global__ __launch_bounds__(NT, 1)
void merge_kernel(const float* __restrict__ W_merge,  // [264,264]
                  const float* __restrict__ b_merge,  // [264]
                  const float* __restrict__ W_cls)    // [264,2]
{
    __shared__ float sw[MERGED * JT];   // [k][jx], 33.8 KB, conflict-free
    __shared__ float sc[BT * MERGED];   // comb rows, 8.4 KB

    const int jt   = blockIdx.x;
    const int b0   = blockIdx.y * BT;
    const int j0   = jt * JT;
    const int tid  = threadIdx.x;
    const int lane = tid & 31;
    const int wid  = tid >> 5;          // = batch group

    // stage comb rows (contiguous copy) with high MLP
    const float* __restrict__ csrc = &g_comb[b0][0];
#pragma unroll
    for (int i = tid; i < BT * MERGED; i += NT) sc[i] = csrc[i];

    // stage W_merge column slice; clamp ragged last tile (masked later)
    const int j  = j0 + lane;
    const int jc = (j < MERGED) ? j : (MERGED - 1);
#pragma unroll 4
    for (int kk = wid; kk < MERGED; kk += 8)
        sw[kk * JT + lane] = W_merge[kk * MERGED + jc];
    __syncthreads();

    // hidden[b0+wid][j] = relu(b_merge[j] + sum_k comb[k]*W[k][j])
    float acc = b_merge[jc];
    const float* __restrict__ scb = &sc[wid * MERGED];
#pragma unroll 8
    for (int k = 0; k < MERGED; k++)
        acc = fmaf(scb[k], sw[k * JT + lane], acc);

    const float rlu = (j < MERGED) ? fmaxf(acc, 0.f) : 0.f;
    float p0 = warp_sum(rlu * W_cls[jc * C + 0]);
    float p1 = warp_sum(rlu * W_cls[jc * C + 1]);
    if (lane == 0) {
        g_partC[b0 + wid][jt][0] = p0;
        g_partC[b0 + wid][jt][1] = p1;
    }
}

// ---------------------------------------------------------------------------
// Kernel 4: final tiny reduction over j-tiles.  grid = 1, block = 256.
// ---------------------------------------------------------------------------
__global__ __launch_bounds__(NT, 1)
void final_kernel(const float* __restrict__ b_cls,
                  float* __restrict__ out)
{
    const int tid = threadIdx.x;     // B*C = 256 exactly
    const int b = tid >> 1, c = tid & 1;
    const float* __restrict__ pc = &g_partC[b][0][0];
    float v = b_cls[c];
#pragma unroll
    for (int jt = 0; jt < JTILES; jt++) v += pc[jt * 2 + c];
    out[tid] = v;
}

extern "C" void kernel_launch(void* const* d_in, const int* in_sizes, int n_in,
                              void* d_out, int out_size)
{
    const float* x        = (const float*)d_in[0];
    const float* stat     = (const float*)d_in[1];
    const float* time_in  = (const float*)d_in[2];
    const int*   smask    = (const int*)  d_in[3];
    const float* W_sensor = (const float*)d_in[4];
    const float* b_sensor = (const float*)d_in[5];
    const float* W_time   = (const float*)d_in[6];
    const float* b_time   = (const float*)d_in[7];
    const float* W_static = (const float*)d_in[8];
    const float* b_static = (const float*)d_in[9];
    const float* W_merge  = (const float*)d_in[10];
    const float* b_merge  = (const float*)d_in[11];
    const float* W_cls    = (const float*)d_in[12];
    const float* b_cls    = (const float*)d_in[13];
    float* out = (float*)d_out;

    reduce_kernel<<<B * PB, NT>>>(x, time_in, smask);
    embed_kernel<<<B, NT>>>(stat, W_sensor, b_sensor, W_time, b_time,
                            W_static, b_static);
    merge_kernel<<<dim3(JTILES, BTILES), NT>>>(W_merge, b_merge, W_cls);
    final_kernel<<<1, NT>>>(b_cls, out);
}